// round 1
// baseline (speedup 1.0000x reference)
#include <cuda_runtime.h>
#include <cstdint>

// SpatialTransformer bilinear flow warp.
// src:  [B,H,W,1] f32,  flow: [B,H,W,2] f32,  out: [B,H,W,1] f32
// B=32, H=768, W=768.
// Each thread handles 4 consecutive pixels along W (W % 4 == 0), so
// flow reads are two float4 loads and the output store is one float4.

#define BB 32
#define HH 768
#define WW 768
#define HW (HH * WW)

__global__ __launch_bounds__(256) void warp_kernel(
    const float* __restrict__ src,
    const float* __restrict__ flow,
    float* __restrict__ out)
{
    const int quad = blockIdx.x * blockDim.x + threadIdx.x; // 4-pixel group id
    const int total_quads = (BB * HW) / 4;
    if (quad >= total_quads) return;

    const int p0  = quad * 4;            // first pixel (linear over B*H*W)
    const int b   = p0 / HW;
    const int rem = p0 - b * HW;
    const int y   = rem / WW;
    const int x0  = rem - y * WW;        // all 4 pixels share row y (W%4==0)

    // flow for 4 pixels: 8 floats = two float4 (flow base is 16B aligned at p0*2)
    const float4 f01 = *reinterpret_cast<const float4*>(flow + (size_t)p0 * 2);
    const float4 f23 = *reinterpret_cast<const float4*>(flow + (size_t)p0 * 2 + 4);

    const float fx[4] = {f01.x, f01.z, f23.x, f23.z};
    const float fy[4] = {f01.y, f01.w, f23.y, f23.w};

    const float* img = src + (size_t)b * HW;

    float4 res;
    float* resp = &res.x;

    #pragma unroll
    for (int i = 0; i < 4; i++) {
        const float gx = (float)(x0 + i) + fx[i];
        const float gy = (float)y + fy[i];

        const float x0f = floorf(gx);
        const float y0f = floorf(gy);
        const float x1f = x0f + 1.0f;
        const float y1f = y0f + 1.0f;

        // weights from UNCLIPPED corners
        const float dx1 = x1f - gx;   // (1 - frac_x)
        const float dx0 = gx - x0f;   // frac_x
        const float dy1 = y1f - gy;
        const float dy0 = gy - y0f;

        const float wa = dx1 * dy1;
        const float wb = dx0 * dy1;
        const float wc = dx1 * dy0;
        const float wd = dx0 * dy0;

        // clipped integer indices
        const int xi0 = (int)fminf(fmaxf(x0f, 0.0f), (float)(WW - 1));
        const int xi1 = (int)fminf(fmaxf(x1f, 0.0f), (float)(WW - 1));
        const int yi0 = (int)fminf(fmaxf(y0f, 0.0f), (float)(HH - 1));
        const int yi1 = (int)fminf(fmaxf(y1f, 0.0f), (float)(HH - 1));

        const float va = __ldg(img + (size_t)yi0 * WW + xi0);
        const float vb = __ldg(img + (size_t)yi0 * WW + xi1);
        const float vc = __ldg(img + (size_t)yi1 * WW + xi0);
        const float vd = __ldg(img + (size_t)yi1 * WW + xi1);

        resp[i] = wa * va + wb * vb + wc * vc + wd * vd;
    }

    *reinterpret_cast<float4*>(out + p0) = res;
}

extern "C" void kernel_launch(void* const* d_in, const int* in_sizes, int n_in,
                              void* d_out, int out_size)
{
    const float* src  = (const float*)d_in[0];
    const float* flow = (const float*)d_in[1];
    float* out = (float*)d_out;

    const int total_quads = (BB * HH * WW) / 4;   // 4,718,592
    const int threads = 256;
    const int blocks  = (total_quads + threads - 1) / threads;
    warp_kernel<<<blocks, threads>>>(src, flow, out);
}

// round 2
// speedup vs baseline: 1.4807x; 1.4807x over previous
#include <cuda_runtime.h>
#include <cstdint>

// SpatialTransformer bilinear flow warp.
// src:  [B,H,W,1] f32,  flow: [B,H,W,2] f32,  out: [B,H,W,1] f32
// B=32, H=768, W=768.
//
// Layout: 2-D tiles of 32x32 pixels per block (256 threads).
//   lane (tx&31)  -> x within tile   (warp covers 32 CONSECUTIVE x -> gathers
//                                     touch 1-2 L1 lines per warp, not 4-5)
//   warp (tx>>5)  -> 4-row vertical strip (rows wy*4 .. wy*4+3) so the
//                    bilinear row halo (y, y+1) is reused in L1 across rows.
// grid = (W/32, H/32, B) = (24, 24, 32)

#define BB 32
#define HH 768
#define WW 768
#define HW (HH * WW)

__global__ __launch_bounds__(256) void warp_kernel(
    const float* __restrict__ src,
    const float* __restrict__ flow,
    float* __restrict__ out)
{
    const int tx   = threadIdx.x;
    const int xg   = blockIdx.x * 32 + (tx & 31);     // global x (warp = 32 consecutive)
    const int yb   = blockIdx.y * 32 + (tx >> 5) * 4; // first of 4 rows for this thread
    const int b    = blockIdx.z;

    const float* img = src + b * HW;
    const float  xgf = (float)xg;

    #pragma unroll
    for (int r = 0; r < 4; r++) {
        const int y   = yb + r;
        const int pix = (b * HH + y) * WW + xg;

        // per-pixel flow (dx, dy): warp reads 256 contiguous bytes
        const float2 f = *reinterpret_cast<const float2*>(flow + (size_t)pix * 2);

        const float gx = xgf + f.x;
        const float gy = (float)y + f.y;

        const float x0f = floorf(gx);
        const float y0f = floorf(gy);
        const float x1f = x0f + 1.0f;
        const float y1f = y0f + 1.0f;

        // bilinear weights from UNCLIPPED corners (matches reference)
        const float dx1 = x1f - gx;
        const float dx0 = gx - x0f;
        const float dy1 = y1f - gy;
        const float dy0 = gy - y0f;

        const float wa = dx1 * dy1;
        const float wb = dx0 * dy1;
        const float wc = dx1 * dy0;
        const float wd = dx0 * dy0;

        // clipped integer indices
        const int xi0 = (int)fminf(fmaxf(x0f, 0.0f), (float)(WW - 1));
        const int xi1 = (int)fminf(fmaxf(x1f, 0.0f), (float)(WW - 1));
        const int yi0 = (int)fminf(fmaxf(y0f, 0.0f), (float)(HH - 1));
        const int yi1 = (int)fminf(fmaxf(y1f, 0.0f), (float)(HH - 1));

        const int r0 = yi0 * WW;
        const int r1 = yi1 * WW;

        const float va = __ldg(img + r0 + xi0);
        const float vb = __ldg(img + r0 + xi1);
        const float vc = __ldg(img + r1 + xi0);
        const float vd = __ldg(img + r1 + xi1);

        out[pix] = wa * va + wb * vb + wc * vc + wd * vd;
    }
}

extern "C" void kernel_launch(void* const* d_in, const int* in_sizes, int n_in,
                              void* d_out, int out_size)
{
    const float* src  = (const float*)d_in[0];
    const float* flow = (const float*)d_in[1];
    float* out = (float*)d_out;

    dim3 grid(WW / 32, HH / 32, BB);   // (24, 24, 32)
    warp_kernel<<<grid, 256>>>(src, flow, out);
}